// round 2
// baseline (speedup 1.0000x reference)
#include <cuda_runtime.h>

#define N_ 16
#define T_ 32
#define D_ 768
#define L_ 196
#define LB 32
#define DC 8
#define NLB 7   // ceil(196/32)

// 16*32*32*196 floats = 12.8 MB scratch for softmaxed attention weights,
// layout attn[((n*T + t)*T + s)*L + l]
__device__ float g_attn[N_ * T_ * T_ * L_];

// ---- packed f32x2 helpers (Blackwell FFMA2 path, PTX-only) ----
__device__ __forceinline__ unsigned long long pack2(float x, float y) {
    unsigned long long r;
    asm("mov.b64 %0, {%1, %2};" : "=l"(r) : "f"(x), "f"(y));
    return r;
}
__device__ __forceinline__ void unpack2(unsigned long long v, float& x, float& y) {
    asm("mov.b64 {%0, %1}, %2;" : "=f"(x), "=f"(y) : "l"(v));
}
__device__ __forceinline__ unsigned long long fma2_(unsigned long long a,
                                                    unsigned long long b,
                                                    unsigned long long c) {
    unsigned long long r;
    asm("fma.rn.f32x2 %0, %1, %2, %3;" : "=l"(r) : "l"(a), "l"(b), "l"(c));
    return r;
}
__device__ __forceinline__ unsigned long long add2_(unsigned long long a,
                                                    unsigned long long b) {
    unsigned long long r;
    asm("add.rn.f32x2 %0, %1, %2;" : "=l"(r) : "l"(a), "l"(b));
    return r;
}

// =====================================================================
// Kernel A: scores + softmax.
// Grid (NLB, N_), 256 threads = 32 l-lanes x 8 t-groups (4 t each).
// Each thread owns S[t0..t0+3][all 32 s][its l] as 4x16 f32x2 accumulators.
// k is staged per 8-d chunk into smem transposed to [dd][l][s] so the
// inner loop reads s-pairs with LDS.64 (conflict-free via +2 pad).
// =====================================================================
__global__ __launch_bounds__(256, 1)
void scores_kernel(const float* __restrict__ q, const float* __restrict__ k,
                   const float* __restrict__ peq, const float* __restrict__ pek)
{
    __shared__ float sk[DC * LB * 34];  // [dd][l][s + 2 pad]

    const int lane = threadIdx.x & 31;
    const int tg   = threadIdx.x >> 5;      // 0..7
    const int l0   = blockIdx.x * LB;
    const int n    = blockIdx.y;
    const int l    = l0 + lane;
    const bool lvalid = (l < L_);
    const int t0   = tg * 4;

    unsigned long long acc[4][16];
#pragma unroll
    for (int i = 0; i < 4; i++)
#pragma unroll
        for (int sp = 0; sp < 16; sp++) acc[i][sp] = 0ULL;

    for (int c = 0; c < D_ / DC; ++c) {
        const int d0 = c * DC;

        // ---- stage k chunk (raw, pos-embed added later): transpose to [dd][l][s]
#pragma unroll
        for (int j = 0; j < 8; j++) {
            int f  = j * 256 + threadIdx.x;   // 0..2047 float4 units
            int c4 = f & 7;
            int r  = f >> 3;                  // 0..255
            int s  = r & 31;
            int dd = r >> 5;
            int lb = 4 * c4;
            float4 v = make_float4(0.f, 0.f, 0.f, 0.f);
            if (l0 + lb < L_)
                v = *reinterpret_cast<const float4*>(
                    &k[((n * T_ + s) * D_ + d0 + dd) * L_ + l0 + lb]);
            float* dst = &sk[dd * (LB * 34) + s];
            dst[(lb + 0) * 34] = v.x;
            dst[(lb + 1) * 34] = v.y;
            dst[(lb + 2) * 34] = v.z;
            dst[(lb + 3) * 34] = v.w;
        }

        // ---- per-thread q chunk (coalesced along l across the warp)
        float qr[4][8];
#pragma unroll
        for (int i = 0; i < 4; i++)
#pragma unroll
            for (int dd = 0; dd < 8; dd++)
                qr[i][dd] = lvalid
                    ? q[((n * T_ + t0 + i) * D_ + d0 + dd) * L_ + l]
                    : 0.f;

        // ---- positional-embed rows for this l, this d-chunk
        float per[8], qer[8];
        if (lvalid) {
            float4 a0 = *reinterpret_cast<const float4*>(&pek[l * D_ + d0]);
            float4 a1 = *reinterpret_cast<const float4*>(&pek[l * D_ + d0 + 4]);
            float4 b0 = *reinterpret_cast<const float4*>(&peq[l * D_ + d0]);
            float4 b1 = *reinterpret_cast<const float4*>(&peq[l * D_ + d0 + 4]);
            per[0] = a0.x; per[1] = a0.y; per[2] = a0.z; per[3] = a0.w;
            per[4] = a1.x; per[5] = a1.y; per[6] = a1.z; per[7] = a1.w;
            qer[0] = b0.x; qer[1] = b0.y; qer[2] = b0.z; qer[3] = b0.w;
            qer[4] = b1.x; qer[5] = b1.y; qer[6] = b1.z; qer[7] = b1.w;
        } else {
#pragma unroll
            for (int dd = 0; dd < 8; dd++) { per[dd] = 0.f; qer[dd] = 0.f; }
        }

        __syncthreads();

        // ---- FFMA2 mainloop: S[t][s-pair] += qp[t] * kp[s-pair]
#pragma unroll
        for (int dd = 0; dd < 8; dd++) {
            unsigned long long pk2 = pack2(per[dd], per[dd]);
            unsigned long long qv[4];
#pragma unroll
            for (int i = 0; i < 4; i++) {
                float qs = qr[i][dd] + qer[dd];
                qv[i] = pack2(qs, qs);
            }
            const unsigned long long* kl =
                reinterpret_cast<const unsigned long long*>(
                    &sk[dd * (LB * 34) + lane * 34]);
#pragma unroll
            for (int sp = 0; sp < 16; sp++) {
                unsigned long long kv = add2_(kl[sp], pk2);
#pragma unroll
                for (int i = 0; i < 4; i++)
                    acc[i][sp] = fma2_(qv[i], kv, acc[i][sp]);
            }
        }
        __syncthreads();
    }

    // ---- softmax over s (fully thread-local) + store attention weights
    if (lvalid) {
        const float scale = rsqrtf((float)D_);
#pragma unroll
        for (int i = 0; i < 4; i++) {
            float v[32];
#pragma unroll
            for (int sp = 0; sp < 16; sp++)
                unpack2(acc[i][sp], v[2 * sp], v[2 * sp + 1]);
            float m = v[0];
#pragma unroll
            for (int s = 1; s < 32; s++) m = fmaxf(m, v[s]);
            float sum = 0.f;
#pragma unroll
            for (int s = 0; s < 32; s++) {
                float e = __expf((v[s] - m) * scale);
                v[s] = e;
                sum += e;
            }
            float inv = 1.f / sum;
            float* ap = &g_attn[((n * T_ + t0 + i) * T_) * L_ + l];
#pragma unroll
            for (int s = 0; s < 32; s++) ap[s * L_] = v[s] * inv;
        }
    }
}

// =====================================================================
// Kernel B: out[n,t,l,d] = sum_s attn[n,t,s,l] * (k[n,s,d,l] + pek[l,d])
// Grid (NLB, N_), 256 threads = 32 l-lanes x 8 t-groups (4 t each).
// attn row A[t, 0..31, l] lives in registers (128/thread, loaded once).
// k staged per 8-d chunk into smem [l][s][dd] so the inner loop reads
// d-pairs with LDS.64; output accumulators packed f32x2 over d-pairs.
// Writes out coalesced along d (float2 per store).
// =====================================================================
__global__ __launch_bounds__(256, 1)
void out_kernel(const float* __restrict__ k, const float* __restrict__ pek,
                float* __restrict__ out)
{
    __shared__ float sk[LB * 258];  // [l][s*8 + dd], +2 pad per l-row

    const int lane = threadIdx.x & 31;
    const int tg   = threadIdx.x >> 5;
    const int l0   = blockIdx.x * LB;
    const int n    = blockIdx.y;
    const int l    = l0 + lane;
    const bool lvalid = (l < L_);
    const int t0   = tg * 4;

    // attention rows for my 4 t's, all 32 s (coalesced along l)
    float ar[4][32];
#pragma unroll
    for (int i = 0; i < 4; i++)
#pragma unroll
        for (int s = 0; s < 32; s++)
            ar[i][s] = lvalid
                ? g_attn[((n * T_ + t0 + i) * T_ + s) * L_ + l]
                : 0.f;

    for (int c = 0; c < D_ / DC; ++c) {
        const int d0 = c * DC;

        // ---- stage k chunk transposed to [l][s][dd]
#pragma unroll
        for (int j = 0; j < 8; j++) {
            int f  = j * 256 + threadIdx.x;
            int c4 = f & 7;
            int r  = f >> 3;      // 0..255
            int dd = r & 7;
            int s  = r >> 3;
            int lb = 4 * c4;
            float4 v = make_float4(0.f, 0.f, 0.f, 0.f);
            if (l0 + lb < L_)
                v = *reinterpret_cast<const float4*>(
                    &k[((n * T_ + s) * D_ + d0 + dd) * L_ + l0 + lb]);
            sk[(lb + 0) * 258 + s * 8 + dd] = v.x;
            sk[(lb + 1) * 258 + s * 8 + dd] = v.y;
            sk[(lb + 2) * 258 + s * 8 + dd] = v.z;
            sk[(lb + 3) * 258 + s * 8 + dd] = v.w;
        }

        float per[8];
        if (lvalid) {
            float4 a0 = *reinterpret_cast<const float4*>(&pek[l * D_ + d0]);
            float4 a1 = *reinterpret_cast<const float4*>(&pek[l * D_ + d0 + 4]);
            per[0] = a0.x; per[1] = a0.y; per[2] = a0.z; per[3] = a0.w;
            per[4] = a1.x; per[5] = a1.y; per[6] = a1.z; per[7] = a1.w;
        } else {
#pragma unroll
            for (int dd = 0; dd < 8; dd++) per[dd] = 0.f;
        }
        unsigned long long pk2[4];
#pragma unroll
        for (int dp = 0; dp < 4; dp++)
            pk2[dp] = pack2(per[2 * dp], per[2 * dp + 1]);

        __syncthreads();

        unsigned long long o2[4][4];
#pragma unroll
        for (int i = 0; i < 4; i++)
#pragma unroll
            for (int dp = 0; dp < 4; dp++) o2[i][dp] = 0ULL;

        const unsigned long long* kl =
            reinterpret_cast<const unsigned long long*>(&sk[lane * 258]);
#pragma unroll
        for (int s = 0; s < 32; s++) {
            unsigned long long kv[4];
#pragma unroll
            for (int dp = 0; dp < 4; dp++)
                kv[dp] = add2_(kl[s * 4 + dp], pk2[dp]);
#pragma unroll
            for (int i = 0; i < 4; i++) {
                unsigned long long a2 = pack2(ar[i][s], ar[i][s]);
#pragma unroll
                for (int dp = 0; dp < 4; dp++)
                    o2[i][dp] = fma2_(a2, kv[dp], o2[i][dp]);
            }
        }

        if (lvalid) {
#pragma unroll
            for (int i = 0; i < 4; i++) {
                float* op = &out[((n * T_ + t0 + i) * L_ + l) * D_ + d0];
#pragma unroll
                for (int dp = 0; dp < 4; dp++) {
                    float x, y;
                    unpack2(o2[i][dp], x, y);
                    *reinterpret_cast<float2*>(&op[2 * dp]) = make_float2(x, y);
                }
            }
        }
        __syncthreads();
    }
}

extern "C" void kernel_launch(void* const* d_in, const int* in_sizes, int n_in,
                              void* d_out, int out_size)
{
    const float* q   = (const float*)d_in[0];
    const float* k   = (const float*)d_in[1];
    const float* peq = (const float*)d_in[2];
    const float* pek = (const float*)d_in[3];
    float* out = (float*)d_out;

    dim3 grid(NLB, N_);
    scores_kernel<<<grid, 256>>>(q, k, peq, pek);
    out_kernel<<<grid, 256>>>(k, pek, out);
}

// round 3
// speedup vs baseline: 1.2962x; 1.2962x over previous
#include <cuda_runtime.h>
#include <cstdint>

#define N_  16
#define T_  32
#define D_  768
#define L_  196
#define DC  4
#define NCH (D_ / DC)   // 192 chunks
#define NLB 7

typedef unsigned long long u64;

// softmaxed attention weights, attn[((n*T + t)*T + s)*L + l]  (12.8 MB)
__device__ float g_attn[N_ * T_ * T_ * L_];

// ---- packed f32x2 helpers (Blackwell FFMA2 path, PTX-only) ----
__device__ __forceinline__ u64 pack2(float x, float y) {
    u64 r; asm("mov.b64 %0, {%1, %2};" : "=l"(r) : "f"(x), "f"(y)); return r;
}
__device__ __forceinline__ void unpack2(u64 v, float& x, float& y) {
    asm("mov.b64 {%0, %1}, %2;" : "=f"(x), "=f"(y) : "l"(v));
}
__device__ __forceinline__ u64 fma2_(u64 a, u64 b, u64 c) {
    u64 r; asm("fma.rn.f32x2 %0, %1, %2, %3;" : "=l"(r) : "l"(a), "l"(b), "l"(c)); return r;
}
__device__ __forceinline__ u64 add2_(u64 a, u64 b) {
    u64 r; asm("add.rn.f32x2 %0, %1, %2;" : "=l"(r) : "l"(a), "l"(b)); return r;
}

// ---- cp.async helpers ----
__device__ __forceinline__ void cp16(void* dst_smem, const float* src) {
    uint32_t d = (uint32_t)__cvta_generic_to_shared(dst_smem);
    asm volatile("cp.async.ca.shared.global [%0], [%1], 16;" :: "r"(d), "l"(src));
}
__device__ __forceinline__ void cp_commit() { asm volatile("cp.async.commit_group;"); }
__device__ __forceinline__ void cp_wait1()  { asm volatile("cp.async.wait_group 1;"); }
__device__ __forceinline__ void cp_wait0()  { asm volatile("cp.async.wait_group 0;"); }

// =====================================================================
// Kernel A: scores + softmax.
// Grid (7, 16, 2) — (l-block, n, t-half). Block 128 = 32 l-lanes x 4 warps,
// each warp owns 4 t's. Raw-k mainloop (pos-embed algebra: only eq·k
// survives the softmax; accumulated in bacc). cp.async double-buffered
// k staging, register-prefetched q.
// =====================================================================
__global__ __launch_bounds__(128, 2)
void scores_kernel(const float* __restrict__ q, const float* __restrict__ k,
                   const float* __restrict__ peq)
{
    __shared__ float sk[2][DC][32][32];   // [buf][dd][s][l]  32 KB
    __shared__ float spe[2][DC][32];      // staged peq [buf][dd][l]

    const int tid  = threadIdx.x;
    const int lane = tid & 31;
    const int tg   = tid >> 5;                 // 0..3
    const int l0   = blockIdx.x * 32;
    const int n    = blockIdx.y;
    const int t0   = blockIdx.z * 16 + tg * 4;
    const int l    = l0 + lane;
    const bool lv  = (l < L_);

    // static per-thread staging map
    const int ll   = (tid & 7) * 4;            // l-quad start
    const bool sv  = (l0 + ll < L_);
    const int pdd  = tid >> 5;                 // 0..3 (for spe stage)
    const int pll  = tid & 31;
    const bool pv_ok = (l0 + pll < L_);

    // zero smem once (invalid slots stay zero for the whole kernel)
    {
        float* s = &sk[0][0][0][0];
        for (int i = tid; i < 2 * DC * 32 * 32; i += 128) s[i] = 0.f;
    }
    __syncthreads();

    auto issue = [&](int c, int buf) {
        const int d0 = c * DC;
#pragma unroll
        for (int i = 0; i < 8; i++) {
            int r  = i * 16 + (tid >> 3);      // 0..127
            int s  = r & 31;
            int dd = r >> 5;
            if (sv)
                cp16(&sk[buf][dd][s][ll],
                     k + ((n * T_ + s) * D_ + d0 + dd) * L_ + l0 + ll);
        }
        spe[buf][pdd][pll] = pv_ok ? peq[(l0 + pll) * D_ + d0 + pdd] : 0.f;
        cp_commit();
    };

    auto loadq = [&](int c, float (&qr)[4][4]) {
        const int d0 = c * DC;
#pragma unroll
        for (int i = 0; i < 4; i++)
#pragma unroll
            for (int dd = 0; dd < 4; dd++)
                qr[i][dd] = lv ? __ldg(q + ((n * T_ + t0 + i) * D_ + d0 + dd) * L_ + l)
                               : 0.f;
    };

    u64 acc[4][16], bacc[16];
#pragma unroll
    for (int i = 0; i < 4; i++)
#pragma unroll
        for (int sp = 0; sp < 16; sp++) acc[i][sp] = 0ULL;
#pragma unroll
    for (int sp = 0; sp < 16; sp++) bacc[sp] = 0ULL;

    float qc[4][4], qn[4][4];
    issue(0, 0);
    loadq(0, qc);

    for (int c = 0; c < NCH; ++c) {
        const int cb = c & 1;
        if (c + 1 < NCH) {
            issue(c + 1, cb ^ 1);
            loadq(c + 1, qn);
            cp_wait1();
        } else {
            cp_wait0();
        }
        __syncthreads();

#pragma unroll
        for (int dd = 0; dd < DC; dd++) {
            float eq = spe[cb][dd][lane];
            u64 ev  = pack2(eq, eq);
            u64 qv0 = pack2(qc[0][dd], qc[0][dd]);
            u64 qv1 = pack2(qc[1][dd], qc[1][dd]);
            u64 qv2 = pack2(qc[2][dd], qc[2][dd]);
            u64 qv3 = pack2(qc[3][dd], qc[3][dd]);
            const float* kb = &sk[cb][dd][0][lane];
#pragma unroll
            for (int sp = 0; sp < 16; sp++) {
                u64 kv = pack2(kb[(2 * sp) * 32], kb[(2 * sp + 1) * 32]);
                bacc[sp]   = fma2_(ev,  kv, bacc[sp]);
                acc[0][sp] = fma2_(qv0, kv, acc[0][sp]);
                acc[1][sp] = fma2_(qv1, kv, acc[1][sp]);
                acc[2][sp] = fma2_(qv2, kv, acc[2][sp]);
                acc[3][sp] = fma2_(qv3, kv, acc[3][sp]);
            }
        }

#pragma unroll
        for (int i = 0; i < 4; i++)
#pragma unroll
            for (int dd = 0; dd < 4; dd++) qc[i][dd] = qn[i][dd];
        __syncthreads();
    }

    // softmax over s (thread-local) with the eq·k correction, store attn
    if (lv) {
        const float scale = 0.03608439182435161f;  // 1/sqrt(768)
        float bv[32];
#pragma unroll
        for (int sp = 0; sp < 16; sp++) unpack2(bacc[sp], bv[2 * sp], bv[2 * sp + 1]);
#pragma unroll
        for (int i = 0; i < 4; i++) {
            float v[32];
#pragma unroll
            for (int sp = 0; sp < 16; sp++) unpack2(acc[i][sp], v[2 * sp], v[2 * sp + 1]);
            float m = -1e30f;
#pragma unroll
            for (int s = 0; s < 32; s++) {
                v[s] = (v[s] + bv[s]) * scale;
                m = fmaxf(m, v[s]);
            }
            float sum = 0.f;
#pragma unroll
            for (int s = 0; s < 32; s++) {
                float e = __expf(v[s] - m);
                v[s] = e;
                sum += e;
            }
            float inv = 1.f / sum;
            float* ap = &g_attn[((n * T_ + t0 + i) * T_) * L_ + l];
#pragma unroll
            for (int s = 0; s < 32; s++) ap[s * L_] = v[s] * inv;
        }
    }
}

// =====================================================================
// Kernel B: out[n,t,l,d] = sum_s attn[n,t,s,l] * k[n,s,d,l] + pek[l,d]
// Grid (7, 16, 2), block 128. attn rows (4 t x 32 s) in registers.
// Raw-k mainloop; pek added once per chunk; chunk pairs buffered so
// stores land as 2 adjacent STG.128 (sector-complete 32B writes).
// =====================================================================
__global__ __launch_bounds__(128, 2)
void out_kernel(const float* __restrict__ k, const float* __restrict__ pek,
                float* __restrict__ out)
{
    __shared__ float sk[2][DC][32][32];
    __shared__ float spe[2][DC][32];

    const int tid  = threadIdx.x;
    const int lane = tid & 31;
    const int tg   = tid >> 5;
    const int l0   = blockIdx.x * 32;
    const int n    = blockIdx.y;
    const int t0   = blockIdx.z * 16 + tg * 4;
    const int l    = l0 + lane;
    const bool lv  = (l < L_);

    const int ll   = (tid & 7) * 4;
    const bool sv  = (l0 + ll < L_);
    const int pdd  = tid >> 5;
    const int pll  = tid & 31;
    const bool pv_ok = (l0 + pll < L_);

    // attention rows for my 4 t's, all 32 s (coalesced along l)
    float ar[4][32];
#pragma unroll
    for (int i = 0; i < 4; i++)
#pragma unroll
        for (int s = 0; s < 32; s++)
            ar[i][s] = lv ? g_attn[((n * T_ + t0 + i) * T_ + s) * L_ + l] : 0.f;

    {
        float* s = &sk[0][0][0][0];
        for (int i = tid; i < 2 * DC * 32 * 32; i += 128) s[i] = 0.f;
    }
    __syncthreads();

    auto issue = [&](int c, int buf) {
        const int d0 = c * DC;
#pragma unroll
        for (int i = 0; i < 8; i++) {
            int r  = i * 16 + (tid >> 3);
            int s  = r & 31;
            int dd = r >> 5;
            if (sv)
                cp16(&sk[buf][dd][s][ll],
                     k + ((n * T_ + s) * D_ + d0 + dd) * L_ + l0 + ll);
        }
        spe[buf][pdd][pll] = pv_ok ? pek[(l0 + pll) * D_ + d0 + pdd] : 0.f;
        cp_commit();
    };

    auto step = [&](int c, u64 (&oc)[4][2]) {
        const int cb = c & 1;
        if (c + 1 < NCH) {
            issue(c + 1, cb ^ 1);
            cp_wait1();
        } else {
            cp_wait0();
        }
        __syncthreads();

        u64 pe0 = pack2(spe[cb][0][lane], spe[cb][1][lane]);
        u64 pe1 = pack2(spe[cb][2][lane], spe[cb][3][lane]);
#pragma unroll
        for (int s = 0; s < 32; s++) {
            u64 kv0 = pack2(sk[cb][0][s][lane], sk[cb][1][s][lane]);
            u64 kv1 = pack2(sk[cb][2][s][lane], sk[cb][3][s][lane]);
#pragma unroll
            for (int i = 0; i < 4; i++) {
                u64 a2 = pack2(ar[i][s], ar[i][s]);
                oc[i][0] = fma2_(a2, kv0, oc[i][0]);
                oc[i][1] = fma2_(a2, kv1, oc[i][1]);
            }
        }
#pragma unroll
        for (int i = 0; i < 4; i++) {
            oc[i][0] = add2_(oc[i][0], pe0);
            oc[i][1] = add2_(oc[i][1], pe1);
        }
        __syncthreads();
    };

    issue(0, 0);

    for (int cc = 0; cc < NCH / 2; ++cc) {
        u64 oA[4][2], oB[4][2];
#pragma unroll
        for (int i = 0; i < 4; i++) {
            oA[i][0] = oA[i][1] = 0ULL;
            oB[i][0] = oB[i][1] = 0ULL;
        }
        step(2 * cc,     oA);   // d = 8*cc .. 8*cc+3
        step(2 * cc + 1, oB);   // d = 8*cc+4 .. 8*cc+7

        if (lv) {
            const int d0 = cc * 8;
#pragma unroll
            for (int i = 0; i < 4; i++) {
                float* op = out + ((n * T_ + t0 + i) * L_ + l) * D_ + d0;
                float4 fa, fb;
                unpack2(oA[i][0], fa.x, fa.y);
                unpack2(oA[i][1], fa.z, fa.w);
                unpack2(oB[i][0], fb.x, fb.y);
                unpack2(oB[i][1], fb.z, fb.w);
                *reinterpret_cast<float4*>(op)     = fa;
                *reinterpret_cast<float4*>(op + 4) = fb;
            }
        }
    }
}

extern "C" void kernel_launch(void* const* d_in, const int* in_sizes, int n_in,
                              void* d_out, int out_size)
{
    const float* q   = (const float*)d_in[0];
    const float* k   = (const float*)d_in[1];
    const float* peq = (const float*)d_in[2];
    const float* pek = (const float*)d_in[3];
    float* out = (float*)d_out;

    dim3 grid(NLB, N_, 2);
    scores_kernel<<<grid, 128>>>(q, k, peq);
    out_kernel<<<grid, 128>>>(k, pek, out);
}